// round 9
// baseline (speedup 1.0000x reference)
#include <cuda_runtime.h>
#include <cstdint>

// Problem constants
static constexpr int B = 32;
static constexpr int L = 4096;
static constexpr int C = 8;
static constexpr int T = 64;
static constexpr long long NELEM = (long long)B * L * C;   // 1,048,576

static constexpr int RED_BLOCKS  = 512;
static constexpr int RED_THREADS = 256;
// 512*256 threads * 8 elems = 1,048,576 == NELEM exactly

// Deterministic scratch (fixed-slot partials)
__device__ double   g_psum[RED_BLOCKS];
__device__ double   g_psumsq[RED_BLOCKS];
__device__ float    g_mean;
__device__ float    g_inv;    // rsqrt.approx(var + eps)
__device__ unsigned g_count = 0;   // last-block-done counter (reset after use)

__device__ __forceinline__ float rsqrt_approx(float x) {
    float r;
    asm("rsqrt.approx.f32 %0, %1;" : "=f"(r) : "f"(x));
    return r;
}

// ---------------------------------------------------------------------------
// K1: partial sums of delta and delta^2 + fused last-block finalize.
// Layout: idx = ((b*L)+l)*C + c, C=8. delta[idx] = in[idx] - in[idx-8]
// (stride C along l), forced 0 at l==0.
// Each thread owns 8 contiguous idx [base, base+8); loads the covering
// window [base-8, base+8) as 4 independent float4s. delta_j = a[j+8]-a[j].
// Head chunk (base % (L*C) == 0) covers exactly the 8 l==0 slots -> whole
// chunk contributes zero.
// Reduction: f32 warp shuffle -> 8 double warp-partials -> warp0 double
// shuffle -> g_psum[block]; last finished block reduces 512 doubles and
// writes g_mean/g_inv (threadFenceReduction pattern, counter reset).
// ---------------------------------------------------------------------------
__global__ void __launch_bounds__(RED_THREADS) reduce_kernel(const float* __restrict__ in) {
    const int tid  = blockIdx.x * blockDim.x + threadIdx.x;
    const int base = tid * 8;
    const bool head = (base & (L * C - 1)) == 0;   // l==0 chunk of a batch row

    float s = 0.0f, q = 0.0f;
    if (!head) {
        const float* p = in + base;
        float4 v0 = *reinterpret_cast<const float4*>(p - 8);
        float4 v1 = *reinterpret_cast<const float4*>(p - 4);
        float4 v2 = *reinterpret_cast<const float4*>(p);
        float4 v3 = *reinterpret_cast<const float4*>(p + 4);
        float a[16] = { v0.x, v0.y, v0.z, v0.w,  v1.x, v1.y, v1.z, v1.w,
                        v2.x, v2.y, v2.z, v2.w,  v3.x, v3.y, v3.z, v3.w };
        #pragma unroll
        for (int j = 0; j < 8; ++j) {
            float delta = a[j + 8] - a[j];
            s += delta;
            q  = fmaf(delta, delta, q);
        }
    }

    // f32 warp reduce (fixed shuffle order -> deterministic)
    #pragma unroll
    for (int o = 16; o > 0; o >>= 1) {
        s += __shfl_down_sync(0xffffffffu, s, o);
        q += __shfl_down_sync(0xffffffffu, q, o);
    }

    __shared__ double ws[8], wq[8];
    const int t    = threadIdx.x;
    const int lane = t & 31;
    const int warp = t >> 5;
    if (lane == 0) { ws[warp] = (double)s; wq[warp] = (double)q; }
    __syncthreads();

    __shared__ bool isLast;
    if (warp == 0) {
        double ds = (lane < 8) ? ws[lane] : 0.0;
        double dq = (lane < 8) ? wq[lane] : 0.0;
        #pragma unroll
        for (int o = 4; o > 0; o >>= 1) {
            ds += __shfl_down_sync(0xffffffffu, ds, o);
            dq += __shfl_down_sync(0xffffffffu, dq, o);
        }
        if (lane == 0) {
            g_psum[blockIdx.x]   = ds;
            g_psumsq[blockIdx.x] = dq;
            __threadfence();
            unsigned prev = atomicAdd(&g_count, 1u);
            isLast = (prev == RED_BLOCKS - 1);
        }
    }
    __syncthreads();

    if (isLast) {
        __threadfence();   // acquire all blocks' partials
        double ds = g_psum[t] + g_psum[t + 256];
        double dq = g_psumsq[t] + g_psumsq[t + 256];
        #pragma unroll
        for (int o = 16; o > 0; o >>= 1) {
            ds += __shfl_down_sync(0xffffffffu, ds, o);
            dq += __shfl_down_sync(0xffffffffu, dq, o);
        }
        __shared__ double fs[8], fq[8];
        if (lane == 0) { fs[warp] = ds; fq[warp] = dq; }
        __syncthreads();
        if (t == 0) {
            double S = 0.0, Q = 0.0;
            #pragma unroll
            for (int w = 0; w < 8; ++w) { S += fs[w]; Q += fq[w]; }
            double mean = S / (double)NELEM;
            double var  = Q / (double)NELEM - mean * mean;
            g_mean  = (float)mean;
            g_inv   = rsqrt_approx((float)var + 1e-5f);
            g_count = 0;   // reset for next graph replay
        }
    }
}

// ---------------------------------------------------------------------------
// K3: main — normalize delta, encode across T=64, LIF recurrence, spike out.
// Occupancy-driven reshape: one thread = 4 consecutive l for one (b, c),
// 1024 CTAs x 256 threads (8192 warps ~ 86% occ; R7 measured grid-limited
// 43% occ / 54% DRAM at 512 CTAs). Warp stores 512B contiguous per t.
// Streaming stores (.cs): output is never re-read.
// out layout: [B, T, C, L] -> ((b*T + t)*C + c)*L + l
// ---------------------------------------------------------------------------
__global__ void __launch_bounds__(256) lif_kernel(
    const float* __restrict__ in,
    const float* __restrict__ enc_w,
    const float* __restrict__ enc_b,
    const float* __restrict__ bn_gamma,
    const float* __restrict__ bn_beta,
    float* __restrict__ out)
{
    __shared__ float sw[T];
    __shared__ float sb[T];
    if (threadIdx.x < T) {
        sw[threadIdx.x] = enc_w[threadIdx.x];   // enc_w is [T,1]
        sb[threadIdx.x] = enc_b[threadIdx.x];
    }
    __syncthreads();

    const int idx = blockIdx.x * blockDim.x + threadIdx.x;  // 0 .. 262143
    const int lv  = idx & ((L / 4) - 1);        // 0..1023
    const int c   = (idx >> 10) & (C - 1);
    const int b   = idx >> 13;
    const int l0  = lv * 4;

    const float mean = g_mean;
    const float inv  = g_inv;
    const float ga   = bn_gamma[0];
    const float be   = bn_beta[0];

    const float* inp = in + ((long long)b * L) * C + c;

    float d[4];
    #pragma unroll
    for (int j = 0; j < 4; ++j) {
        int l = l0 + j;
        float delta = (l == 0) ? 0.0f : (inp[l * C] - inp[(l - 1) * C]);
        float x = (delta - mean) * inv;
        d[j] = x * ga + be;
    }

    float v0 = 0.f, v1 = 0.f, v2 = 0.f, v3 = 0.f;
    float* op = out + (((long long)b * T) * C + c) * L + l0;

    #pragma unroll 8
    for (int t = 0; t < T; ++t) {
        const float w  = sw[t];
        const float bb = sb[t];
        float4 s4;

        float x;
        x = fmaf(d[0], w, bb); v0 = v0 + (x - v0) * 0.5f;
        bool p0 = (v0 >= 1.0f); s4.x = p0 ? 1.0f : 0.0f; v0 = p0 ? 0.0f : v0;
        x = fmaf(d[1], w, bb); v1 = v1 + (x - v1) * 0.5f;
        bool p1 = (v1 >= 1.0f); s4.y = p1 ? 1.0f : 0.0f; v1 = p1 ? 0.0f : v1;
        x = fmaf(d[2], w, bb); v2 = v2 + (x - v2) * 0.5f;
        bool p2 = (v2 >= 1.0f); s4.z = p2 ? 1.0f : 0.0f; v2 = p2 ? 0.0f : v2;
        x = fmaf(d[3], w, bb); v3 = v3 + (x - v3) * 0.5f;
        bool p3 = (v3 >= 1.0f); s4.w = p3 ? 1.0f : 0.0f; v3 = p3 ? 0.0f : v3;

        __stcs(reinterpret_cast<float4*>(op + (long long)t * (C * L)), s4);
    }
}

// ---------------------------------------------------------------------------
extern "C" void kernel_launch(void* const* d_in, const int* in_sizes, int n_in,
                              void* d_out, int out_size)
{
    const float* in       = (const float*)d_in[0];
    const float* bn_gamma = (const float*)d_in[1];
    const float* bn_beta  = (const float*)d_in[2];
    const float* enc_w    = (const float*)d_in[3];
    const float* enc_b    = (const float*)d_in[4];
    float* out            = (float*)d_out;

    reduce_kernel<<<RED_BLOCKS, RED_THREADS>>>(in);

    const int total_thr = B * C * (L / 4);      // 262144
    lif_kernel<<<total_thr / 256, 256>>>(in, enc_w, enc_b, bn_gamma, bn_beta, out);
}

// round 10
// speedup vs baseline: 1.3354x; 1.3354x over previous
#include <cuda_runtime.h>
#include <cstdint>

// Problem constants
static constexpr int B = 32;
static constexpr int L = 4096;
static constexpr int C = 8;
static constexpr int T = 64;
static constexpr long long NELEM = (long long)B * L * C;   // 1,048,576

static constexpr int RED_BLOCKS  = 256;
static constexpr int RED_THREADS = 256;
// 256*256 threads * 16 elems = 1,048,576 == NELEM exactly

// Deterministic scratch (fixed-slot partials)
__device__ double   g_psum[RED_BLOCKS];
__device__ double   g_psumsq[RED_BLOCKS];
__device__ float    g_mean;
__device__ float    g_inv;    // rsqrt.approx(var + eps)
__device__ unsigned g_count = 0;   // last-block-done counter (reset after use)

__device__ __forceinline__ float rsqrt_approx(float x) {
    float r;
    asm("rsqrt.approx.f32 %0, %1;" : "=f"(r) : "f"(x));
    return r;
}

// ---------------------------------------------------------------------------
// K1: partial sums of delta and delta^2 + fused last-block finalize.
// (R7 configuration verbatim — proven.)
// Layout: idx = ((b*L)+l)*C + c, C=8. delta[idx] = in[idx] - in[idx-8]
// (stride C along l), forced 0 at l==0.
// Each thread owns 16 contiguous idx; loads window [base-8, base+16) as 6
// independent float4s. delta_j = a[j+8] - a[j]; head chunk zeroes j<8.
// f32 warp shuffle -> double warp partials -> double block result; last
// finished block reduces the 256 doubles and writes g_mean/g_inv.
// ---------------------------------------------------------------------------
__global__ void __launch_bounds__(RED_THREADS) reduce_kernel(const float* __restrict__ in) {
    const int tid  = blockIdx.x * blockDim.x + threadIdx.x;
    const int base = tid * 16;
    const float* p = in + base;

    float4 v0, v1, v2, v3, v4, v5;
    v2 = *reinterpret_cast<const float4*>(p);
    v3 = *reinterpret_cast<const float4*>(p + 4);
    v4 = *reinterpret_cast<const float4*>(p + 8);
    v5 = *reinterpret_cast<const float4*>(p + 12);
    if (base == 0) {
        v0 = make_float4(0.f, 0.f, 0.f, 0.f);
        v1 = v0;
    } else {
        v0 = *reinterpret_cast<const float4*>(p - 8);
        v1 = *reinterpret_cast<const float4*>(p - 4);
    }

    float a[24] = { v0.x, v0.y, v0.z, v0.w,  v1.x, v1.y, v1.z, v1.w,
                    v2.x, v2.y, v2.z, v2.w,  v3.x, v3.y, v3.z, v3.w,
                    v4.x, v4.y, v4.z, v4.w,  v5.x, v5.y, v5.z, v5.w };

    const bool head = (base & (L * C - 1)) == 0;   // first 16-chunk of a batch row
    float s = 0.0f, q = 0.0f;
    #pragma unroll
    for (int j = 0; j < 16; ++j) {
        float delta = a[j + 8] - a[j];
        if (head && j < 8) delta = 0.0f;
        s += delta;
        q  = fmaf(delta, delta, q);
    }

    #pragma unroll
    for (int o = 16; o > 0; o >>= 1) {
        s += __shfl_down_sync(0xffffffffu, s, o);
        q += __shfl_down_sync(0xffffffffu, q, o);
    }

    __shared__ double ws[8], wq[8];
    const int t    = threadIdx.x;
    const int lane = t & 31;
    const int warp = t >> 5;
    if (lane == 0) { ws[warp] = (double)s; wq[warp] = (double)q; }
    __syncthreads();

    __shared__ bool isLast;
    if (warp == 0) {
        double ds = (lane < 8) ? ws[lane] : 0.0;
        double dq = (lane < 8) ? wq[lane] : 0.0;
        #pragma unroll
        for (int o = 4; o > 0; o >>= 1) {
            ds += __shfl_down_sync(0xffffffffu, ds, o);
            dq += __shfl_down_sync(0xffffffffu, dq, o);
        }
        if (lane == 0) {
            g_psum[blockIdx.x]   = ds;
            g_psumsq[blockIdx.x] = dq;
            __threadfence();
            unsigned prev = atomicAdd(&g_count, 1u);
            isLast = (prev == RED_BLOCKS - 1);
        }
    }
    __syncthreads();

    if (isLast) {
        __threadfence();   // acquire all blocks' partials
        double ds = g_psum[t];
        double dq = g_psumsq[t];
        #pragma unroll
        for (int o = 16; o > 0; o >>= 1) {
            ds += __shfl_down_sync(0xffffffffu, ds, o);
            dq += __shfl_down_sync(0xffffffffu, dq, o);
        }
        __shared__ double fs[8], fq[8];
        if (lane == 0) { fs[warp] = ds; fq[warp] = dq; }
        __syncthreads();
        if (t == 0) {
            double S = 0.0, Q = 0.0;
            #pragma unroll
            for (int w = 0; w < 8; ++w) { S += fs[w]; Q += fq[w]; }
            double mean = S / (double)NELEM;
            double var  = Q / (double)NELEM - mean * mean;
            g_mean  = (float)mean;
            g_inv   = rsqrt_approx((float)var + 1e-5f);
            g_count = 0;   // reset for next graph replay
        }
    }
}

// ---------------------------------------------------------------------------
// K3: main — normalize delta, encode across T=64, LIF recurrence, spike out.
// Per-thread shape IDENTICAL to R7 (8 l's as two disjoint 4-chunks, two
// independent 512B-burst float4 .cs stores per t — proven 49us).
// Only change: 1024 CTAs x 128 threads instead of 512 x 256. Same 4096
// warps, same warp-level store pattern, but CTAs/SM goes 3.46 (max 4, 15%
// tail waste) -> 6.92 (max 7, ~1% waste). Wave-balance fix, not occupancy.
// out layout: [B, T, C, L] -> ((b*T + t)*C + c)*L + l
// ---------------------------------------------------------------------------
__global__ void __launch_bounds__(128) lif_kernel(
    const float* __restrict__ in,
    const float* __restrict__ enc_w,
    const float* __restrict__ enc_b,
    const float* __restrict__ bn_gamma,
    const float* __restrict__ bn_beta,
    float* __restrict__ out)
{
    __shared__ float sw[T];
    __shared__ float sb[T];
    if (threadIdx.x < T) {
        sw[threadIdx.x] = enc_w[threadIdx.x];   // enc_w is [T,1]
        sb[threadIdx.x] = enc_b[threadIdx.x];
    }
    __syncthreads();

    const int idx = blockIdx.x * blockDim.x + threadIdx.x;  // 0 .. 131071
    const int lv  = idx & ((L / 8) - 1);        // 0..511
    const int c   = (idx >> 9) & (C - 1);
    const int b   = idx >> 12;
    const int lA  = lv * 4;                     // chunk A: [lA, lA+4)
    const int lB  = lA + (L / 2);               // chunk B: [lB, lB+4)

    const float mean = g_mean;
    const float inv  = g_inv;
    const float ga   = bn_gamma[0];
    const float be   = bn_beta[0];

    const float* inp = in + ((long long)b * L) * C + c;

    float dA[4], dB[4];
    #pragma unroll
    for (int j = 0; j < 4; ++j) {
        int la = lA + j;
        float deltaA = (la == 0) ? 0.0f : (inp[la * C] - inp[(la - 1) * C]);
        float xa = (deltaA - mean) * inv;
        dA[j] = xa * ga + be;

        int lb = lB + j;
        float deltaB = inp[lb * C] - inp[(lb - 1) * C];   // lB >= 2048, never 0
        float xb = (deltaB - mean) * inv;
        dB[j] = xb * ga + be;
    }

    float vA0 = 0.f, vA1 = 0.f, vA2 = 0.f, vA3 = 0.f;
    float vB0 = 0.f, vB1 = 0.f, vB2 = 0.f, vB3 = 0.f;

    float* opA = out + (((long long)b * T) * C + c) * L + lA;
    float* opB = opA + (L / 2);

    #pragma unroll 8
    for (int t = 0; t < T; ++t) {
        const float w  = sw[t];
        const float bb = sb[t];
        const long long off = (long long)t * (C * L);
        float4 sa, sbv;

        float x;
        x = fmaf(dA[0], w, bb); vA0 = vA0 + (x - vA0) * 0.5f;
        bool p0 = (vA0 >= 1.0f); sa.x = p0 ? 1.0f : 0.0f; vA0 = p0 ? 0.0f : vA0;
        x = fmaf(dA[1], w, bb); vA1 = vA1 + (x - vA1) * 0.5f;
        bool p1 = (vA1 >= 1.0f); sa.y = p1 ? 1.0f : 0.0f; vA1 = p1 ? 0.0f : vA1;
        x = fmaf(dA[2], w, bb); vA2 = vA2 + (x - vA2) * 0.5f;
        bool p2 = (vA2 >= 1.0f); sa.z = p2 ? 1.0f : 0.0f; vA2 = p2 ? 0.0f : vA2;
        x = fmaf(dA[3], w, bb); vA3 = vA3 + (x - vA3) * 0.5f;
        bool p3 = (vA3 >= 1.0f); sa.w = p3 ? 1.0f : 0.0f; vA3 = p3 ? 0.0f : vA3;

        x = fmaf(dB[0], w, bb); vB0 = vB0 + (x - vB0) * 0.5f;
        bool q0 = (vB0 >= 1.0f); sbv.x = q0 ? 1.0f : 0.0f; vB0 = q0 ? 0.0f : vB0;
        x = fmaf(dB[1], w, bb); vB1 = vB1 + (x - vB1) * 0.5f;
        bool q1 = (vB1 >= 1.0f); sbv.y = q1 ? 1.0f : 0.0f; vB1 = q1 ? 0.0f : vB1;
        x = fmaf(dB[2], w, bb); vB2 = vB2 + (x - vB2) * 0.5f;
        bool q2 = (vB2 >= 1.0f); sbv.z = q2 ? 1.0f : 0.0f; vB2 = q2 ? 0.0f : vB2;
        x = fmaf(dB[3], w, bb); vB3 = vB3 + (x - vB3) * 0.5f;
        bool q3 = (vB3 >= 1.0f); sbv.w = q3 ? 1.0f : 0.0f; vB3 = q3 ? 0.0f : vB3;

        __stcs(reinterpret_cast<float4*>(opA + off), sa);
        __stcs(reinterpret_cast<float4*>(opB + off), sbv);
    }
}

// ---------------------------------------------------------------------------
extern "C" void kernel_launch(void* const* d_in, const int* in_sizes, int n_in,
                              void* d_out, int out_size)
{
    const float* in       = (const float*)d_in[0];
    const float* bn_gamma = (const float*)d_in[1];
    const float* bn_beta  = (const float*)d_in[2];
    const float* enc_w    = (const float*)d_in[3];
    const float* enc_b    = (const float*)d_in[4];
    float* out            = (float*)d_out;

    reduce_kernel<<<RED_BLOCKS, RED_THREADS>>>(in);

    const int total_thr = B * C * (L / 8);      // 131072
    lif_kernel<<<total_thr / 128, 128>>>(in, enc_w, enc_b, bn_gamma, bn_beta, out);
}